// round 14
// baseline (speedup 1.0000x reference)
#include <cuda_runtime.h>
#include <math.h>

#define NN 512
#define EE 512
#define MM 16384
#define FINW 64
#define RTOT (EE*EE)   // 262144
#define SMAX 16384

typedef unsigned long long ull;

// packed f32x2 helpers (sm_90+/sm_103a PTX; FFMA2 in SASS)
#define PACK2(d, lo, hi) asm("mov.b64 %0, {%1,%2};" : "=l"(d) : "f"(lo), "f"(hi))
#define UNPACK2(lo, hi, s) asm("mov.b64 {%0,%1}, %2;" : "=f"(lo), "=f"(hi) : "l"(s))
#define FMA2(d, a, b, c) asm("fma.rn.f32x2 %0, %1, %2, %3;" : "=l"(d) : "l"(a), "l"(b), "l"(c))

// ---------------- scratch (device globals) ----------------
struct SmallBufs {          // zeroed with ONE memset
    float rowS1[EE*64];
    float colS2[EE*64];
    float Hrow[EE*128];
    float Hcol[EE*128];
    float segx[NN*3];
    float cnt[NN];
    float nbt0[NN*FINW];
    int   cntA[EE];
    int   cntB[EE];
};
__device__ SmallBufs g_sb;

__device__ float g_efn[EE*FINW];
__device__ float g_cdiff[EE*3];
__device__ int   g_map[RTOT];          // 0 = empty, else slot+1
__device__ int   g_cells[SMAX];
__device__ int   g_nnz;
__device__ float g_Tval[(size_t)SMAX*96];
__device__ float g_S1[(size_t)SMAX*64];
__device__ float g_S2[(size_t)SMAX*64];
__device__ float g_c1[64], g_c2[64], g_u0[128];
__device__ float g_atab[EE*128], g_btab[EE*128];
__device__ int   g_offA[EE], g_offB[EE], g_curA[EE], g_curB[EE];
__device__ int   g_listA[SMAX], g_listB[SMAX];
__device__ float g_SS[(size_t)RTOT*64];     // 64 MB
__device__ float g_Ztc[(size_t)SMAX*128];   // 8 MB
__device__ float g_Hdiag[EE*128];
__device__ float g_diag[EE*FINW], g_row[EE*FINW], g_col[EE*FINW];
__device__ float g_tot[FINW], g_tr[FINW];

__device__ __forceinline__ float siluf(float v) {
    return v * __fdividef(1.f, 1.f + __expf(-v));
}

// vector fp32 reduction (sm_90+): one instruction, 16B payload
__device__ __forceinline__ void red4(float* addr, float a, float b, float c, float d) {
    asm volatile("red.global.add.v4.f32 [%0], {%1,%2,%3,%4};"
                 :: "l"(addr), "f"(a), "f"(b), "f"(c), "f"(d) : "memory");
}

// ---------------- 1. edge encoder + coord_diff (+ c1/c2 constants in last block) ----------------
__global__ void k_edge(const float* __restrict__ h, const float* __restrict__ x,
                       const int* __restrict__ edges,
                       const float* __restrict__ ew1, const float* __restrict__ eb1,
                       const float* __restrict__ ew2, const float* __restrict__ eb2,
                       const float* __restrict__ p1b1, const float* __restrict__ p1w2,
                       const float* __restrict__ p1b2,
                       const float* __restrict__ p2b1, const float* __restrict__ p2w2,
                       const float* __restrict__ p2b2)
{
    __shared__ float hcat[128];
    __shared__ float hid[128];
    int e = blockIdx.x, t = threadIdx.x;
    if (e == EE) {   // c1/c2 constants
        hcat[t] = siluf(p1b1[t]);
        hid[t]  = siluf(p2b1[t]);
        __syncthreads();
        if (t < 64) {
            float a = p1b2[t], b = p2b2[t];
#pragma unroll 8
            for (int k = 0; k < 128; k++) { a += hcat[k]*p1w2[k*64+t]; b += hid[k]*p2w2[k*64+t]; }
            g_c1[t] = a; g_c2[t] = b;
        }
        return;
    }
    int r = edges[e], c = edges[EE + e];
    if (t < 64) hcat[t] = h[r*64 + t];
    else        hcat[t] = h[c*64 + (t - 64)];
    if (t < 3)  g_cdiff[e*3 + t] = x[r*3 + t] - x[c*3 + t];
    __syncthreads();
    float acc = eb1[t];
#pragma unroll 8
    for (int k = 0; k < 128; k++) acc += hcat[k] * ew1[k*128 + t];
    hid[t] = siluf(acc);
    __syncthreads();
    if (t < 64) {
        float o = eb2[t];
#pragma unroll 8
        for (int k = 0; k < 128; k++) o += hid[k] * ew2[k*64 + t];
        g_efn[e*64 + t] = o;
    }
}

// ---------------- 2. occupancy flag + compaction ----------------
__global__ void k_flag(const int* __restrict__ nbe)
{
    int m = blockIdx.x * blockDim.x + threadIdx.x;
    if (m < MM) g_map[nbe[m]*EE + nbe[MM + m]] = 1;
}

__global__ void k_compact()
{
    int cell = blockIdx.x * blockDim.x + threadIdx.x;
    if (cell < RTOT && g_map[cell] != 0) {
        int slot = atomicAdd(&g_nnz, 1);
        g_map[cell] = slot + 1;
        g_cells[slot] = cell;
    }
}

// ---------------- 3. VTV + PE + scatter into compact T ----------------
__global__ void k_scat(const int* __restrict__ nbe)
{
    int m = blockIdx.x, f = threadIdx.x;  // 128 threads, 96 active
    if (f >= 96) return;
    int a = nbe[m], b = nbe[MM + m];
    float val;
    if (f < 32) {
        float vtv = 0.f;
#pragma unroll
        for (int d = 0; d < 3; d++) vtv += g_cdiff[a*3 + d] * g_cdiff[b*3 + d];
        int i = f >> 1;
        float ang = vtv * 16.f * expf(-0.5756462732485115f * (float)i);
        val = (f & 1) ? cosf(ang) : sinf(ang);
    } else {
        val = g_efn[a*64 + (f - 32)] * g_efn[b*64 + (f - 32)];
    }
    int slot = g_map[a*EE + b] - 1;
    atomicAdd(&g_Tval[(size_t)slot*96 + f], val);
}

// ---------------- fused 2-layer MLP, W2 overlaid on sA+W1 region ----------------
template<int K1>
__device__ __forceinline__ void mlp_tile(float* region, float* sHid,
    const float* __restrict__ W1, const float* __restrict__ b1,
    const float* __restrict__ W2, const float* __restrict__ b2,
    float acc2[4][4])
{
    float* sA  = region;
    float* sW1 = region + 64*K1;
    int tid = threadIdx.x, ty = tid >> 4, tx = tid & 15;
    ull accp[4][4];
#pragma unroll
    for (int i = 0; i < 4; i++)
#pragma unroll
        for (int u = 0; u < 4; u++) accp[i][u] = 0ull;

    for (int kc = 0; kc < K1; kc += 32) {
        for (int i = tid*4; i < 32*128; i += 1024)
            *(float4*)&sW1[i] = *(const float4*)&W1[kc*128 + i];
        __syncthreads();
#pragma unroll 8
        for (int k = 0; k < 32; k++) {
            ulonglong2 b0 = *(const ulonglong2*)&sW1[k*128 + tx*8];
            ulonglong2 b1v = *(const ulonglong2*)&sW1[k*128 + tx*8 + 4];
#pragma unroll
            for (int i = 0; i < 4; i++) {
                float av = sA[(ty*4 + i)*K1 + kc + k];
                ull ap; PACK2(ap, av, av);
                FMA2(accp[i][0], ap, b0.x, accp[i][0]);
                FMA2(accp[i][1], ap, b0.y, accp[i][1]);
                FMA2(accp[i][2], ap, b1v.x, accp[i][2]);
                FMA2(accp[i][3], ap, b1v.y, accp[i][3]);
            }
        }
        __syncthreads();
    }
#pragma unroll
    for (int i = 0; i < 4; i++)
#pragma unroll
        for (int u = 0; u < 4; u++) {
            float lo, hi; UNPACK2(lo, hi, accp[i][u]);
            int j = tx*8 + u*2;
            sHid[(ty*4 + i)*128 + j]     = siluf(lo + b1[j]);
            sHid[(ty*4 + i)*128 + j + 1] = siluf(hi + b1[j + 1]);
        }
    __syncthreads();
    for (int i = tid*4; i < 128*64; i += 1024)
        *(float4*)&region[i] = *(const float4*)&W2[i];
    __syncthreads();

    ull acc2p[4][2];
#pragma unroll
    for (int i = 0; i < 4; i++) { acc2p[i][0] = 0ull; acc2p[i][1] = 0ull; }
#pragma unroll 8
    for (int k = 0; k < 128; k++) {
        ulonglong2 b = *(const ulonglong2*)&region[k*64 + tx*4];
#pragma unroll
        for (int i = 0; i < 4; i++) {
            float av = sHid[(ty*4 + i)*128 + k];
            ull ap; PACK2(ap, av, av);
            FMA2(acc2p[i][0], ap, b.x, acc2p[i][0]);
            FMA2(acc2p[i][1], ap, b.y, acc2p[i][1]);
        }
    }
#pragma unroll
    for (int i = 0; i < 4; i++) {
        float lo, hi;
        UNPACK2(lo, hi, acc2p[i][0]);
        acc2[i][0] = lo + b2[tx*4];     acc2[i][1] = hi + b2[tx*4 + 1];
        UNPACK2(lo, hi, acc2p[i][1]);
        acc2[i][2] = lo + b2[tx*4 + 2]; acc2[i][3] = hi + b2[tx*4 + 3];
    }
    __syncthreads();
}

// ---------------- 5. sparse MLPs: S1,S2 + row/col sums (v4 REDs) ----------------
__global__ void __launch_bounds__(256, 3) k_smlp(
    const float* __restrict__ p1w1, const float* __restrict__ p1b1,
    const float* __restrict__ p1w2, const float* __restrict__ p1b2,
    const float* __restrict__ p2w1, const float* __restrict__ p2b1,
    const float* __restrict__ p2w2, const float* __restrict__ p2b2)
{
    extern __shared__ float smem[];
    float* sHid   = smem;            // 8192
    float* region = smem + 8192;     // 64*96 + 32*128 = 10240
    int base = blockIdx.x * 64;
    int tid = threadIdx.x, ty = tid >> 4, tx = tid & 15;
    int nnz = g_nnz;

    const float* Tp = &g_Tval[(size_t)base * 96];
    for (int i = tid*4; i < 64*96; i += 1024)
        *(float4*)&region[i] = *(const float4*)&Tp[i];
    __syncthreads();

    float4 c1v = *(const float4*)&g_c1[tx*4];
    float4 c2v = *(const float4*)&g_c2[tx*4];

    float acc2[4][4];
    mlp_tile<96>(region, sHid, p1w1, p1b1, p1w2, p1b2, acc2);
#pragma unroll
    for (int i = 0; i < 4; i++) {
        int slot = base + ty*4 + i;
        if (slot < nnz) {
            int cell = g_cells[slot];
            float v0 = acc2[i][0] - c1v.x, v1 = acc2[i][1] - c1v.y;
            float v2 = acc2[i][2] - c1v.z, v3 = acc2[i][3] - c1v.w;
            *(float4*)&g_S1[(size_t)slot*64 + tx*4] = make_float4(v0, v1, v2, v3);
            red4(&g_sb.rowS1[(cell >> 9)*64 + tx*4], v0, v1, v2, v3);
        }
    }
    __syncthreads();
    for (int i = tid*4; i < 64*96; i += 1024)
        *(float4*)&region[i] = *(const float4*)&Tp[i];
    __syncthreads();

    mlp_tile<96>(region, sHid, p2w1, p2b1, p2w2, p2b2, acc2);
#pragma unroll
    for (int i = 0; i < 4; i++) {
        int slot = base + ty*4 + i;
        if (slot < nnz) {
            int cell = g_cells[slot];
            float v0 = acc2[i][0] - c2v.x, v1 = acc2[i][1] - c2v.y;
            float v2 = acc2[i][2] - c2v.z, v3 = acc2[i][3] - c2v.w;
            *(float4*)&g_S2[(size_t)slot*64 + tx*4] = make_float4(v0, v1, v2, v3);
            red4(&g_sb.colS2[(cell & 511)*64 + tx*4], v0, v1, v2, v3);
        }
    }
}

// ---------------- 6. a_i / b_j tables (+ u0 in last block) ----------------
__global__ void k_ab(const float* __restrict__ p3w1, const float* __restrict__ p3b1)
{
    __shared__ float r[64];
    int b = blockIdx.x, t = threadIdx.x;  // 128
    if (b < 512) {
        int i = b;
        if (t < 64) r[t] = g_sb.rowS1[i*64 + t] * g_c2[t];
        __syncthreads();
        float a = 0.f;
#pragma unroll 8
        for (int f = 0; f < 64; f++) a += r[f] * p3w1[(96+f)*128 + t];
        g_atab[i*128 + t] = a;
    } else if (b < 1024) {
        int j = b - 512;
        if (t < 64) r[t] = g_sb.colS2[j*64 + t] * g_c1[t];
        __syncthreads();
        float a = 0.f;
#pragma unroll 8
        for (int f = 0; f < 64; f++) a += r[f] * p3w1[(96+f)*128 + t];
        g_btab[j*128 + t] = a;
    } else {
        if (t < 64) r[t] = 512.f * g_c1[t] * g_c2[t];
        __syncthreads();
        float u = p3b1[t];
#pragma unroll 8
        for (int f = 0; f < 64; f++) u += r[f] * p3w1[(96+f)*128 + t];
        g_u0[t] = u;
    }
}

// ---------------- 7. group slots by middle index ----------------
__global__ void k_cnt()
{
    int s = blockIdx.x * blockDim.x + threadIdx.x;
    if (s < g_nnz) {
        int cell = g_cells[s];
        atomicAdd(&g_sb.cntA[cell & 511], 1);
        atomicAdd(&g_sb.cntB[cell >> 9], 1);
    }
}

__global__ void k_scan()
{
    __shared__ int s[512];
    int t = threadIdx.x;  // 512
    s[t] = g_sb.cntA[t]; __syncthreads();
    for (int d = 1; d < 512; d <<= 1) {
        int v = (t >= d) ? s[t - d] : 0;
        __syncthreads();
        s[t] += v;
        __syncthreads();
    }
    int exc = s[t] - g_sb.cntA[t];
    g_offA[t] = exc; g_curA[t] = exc;
    __syncthreads();
    s[t] = g_sb.cntB[t]; __syncthreads();
    for (int d = 1; d < 512; d <<= 1) {
        int v = (t >= d) ? s[t - d] : 0;
        __syncthreads();
        s[t] += v;
        __syncthreads();
    }
    exc = s[t] - g_sb.cntB[t];
    g_offB[t] = exc; g_curB[t] = exc;
}

__global__ void k_fill()
{
    int s = blockIdx.x * blockDim.x + threadIdx.x;
    if (s < g_nnz) {
        int cell = g_cells[s];
        int pa = atomicAdd(&g_curA[cell & 511], 1);
        g_listA[pa] = s;
        int pb = atomicAdd(&g_curB[cell >> 9], 1);
        g_listB[pb] = s;
    }
}

// ---------------- 8. sparse-sparse product, f-split (grid 512 x 2) ----------------
__global__ void __launch_bounds__(256) k_ss()
{
    __shared__ float sA[64*32];
    __shared__ float sB[64*32];
    __shared__ int ri[64], cj[64];
    int k = blockIdx.x, tid = threadIdx.x;
    int f0 = blockIdx.y * 32;
    int cA = g_sb.cntA[k], cB = g_sb.cntB[k];
    if (cA == 0 || cB == 0) return;
    int oA = g_offA[k], oB = g_offB[k];

    for (int a0 = 0; a0 < cA; a0 += 64) {
        int nA = min(64, cA - a0);
        __syncthreads();
        for (int x = tid; x < nA*32; x += 256) {
            int r = x >> 5;
            int slot = g_listA[oA + a0 + r];
            sA[x] = g_S1[(size_t)slot*64 + f0 + (x & 31)];
        }
        for (int r = tid; r < nA; r += 256) ri[r] = g_cells[g_listA[oA + a0 + r]] >> 9;
        for (int b0 = 0; b0 < cB; b0 += 64) {
            int nB = min(64, cB - b0);
            __syncthreads();
            for (int x = tid; x < nB*32; x += 256) {
                int c = x >> 5;
                int slot = g_listB[oB + b0 + c];
                sB[x] = g_S2[(size_t)slot*64 + f0 + (x & 31)];
            }
            for (int c = tid; c < nB; c += 256) cj[c] = g_cells[g_listB[oB + b0 + c]] & 511;
            __syncthreads();
            int fg = tid & 7, pc = tid >> 3;
            for (int r = 0; r < nA; r++) {
                float4 av = *(const float4*)&sA[r*32 + fg*4];
                int ibase = ri[r];
                for (int c = pc; c < nB; c += 32) {
                    float4 bv = *(const float4*)&sB[c*32 + fg*4];
                    red4(&g_SS[((size_t)ibase*512 + cj[c])*64 + f0 + fg*4],
                         av.x*bv.x, av.y*bv.y, av.z*bv.z, av.w*bv.w);
                }
            }
        }
    }
}

// ---------------- 9. Ztc[slot] = W1t^T Tval[slot] ----------------
__global__ void k_tc(const float* __restrict__ p3w1)
{
    __shared__ float tv[96];
    int slot = blockIdx.x, t = threadIdx.x;  // 128
    if (slot >= g_nnz) return;
    if (t < 96) tv[t] = g_Tval[(size_t)slot*96 + t];
    __syncthreads();
    float acc = 0.f;
#pragma unroll 8
    for (int k = 0; k < 96; k++) acc += tv[k] * p3w1[k*128 + t];
    g_Ztc[(size_t)slot*128 + t] = acc;
}

// ---------------- 10. FUSED: Z-GEMM, 2 i-rows per block, reg col-accumulators ----------------
__global__ void __launch_bounds__(256) k_fused(const float* __restrict__ p3w1)
{
    extern __shared__ float dsm[];
    float* sA   = dsm;                  // [64][68]
    float* sB   = sA + 64*68;           // [64][128]  W1m
    float* srow = sB + 8192;            // [128]
    int*  sslot = (int*)(srow + 128);   // [64]

    int blk = blockIdx.x;               // 2048 blocks
    int j0 = (blk & 7) << 6;
    int i0 = (blk >> 3) * 2;
    int tid = threadIdx.x;
    int ty = tid >> 4, tx = tid & 15;

    for (int x = tid*4; x < 8192; x += 1024)
        *(float4*)&sB[x] = *(const float4*)&p3w1[96*128 + x];

    float colsum[4][8];
#pragma unroll
    for (int i4 = 0; i4 < 4; i4++)
#pragma unroll
        for (int u = 0; u < 8; u++) colsum[i4][u] = 0.f;

    for (int it = 0; it < 2; it++) {
        int i_glob = i0 + it;
        size_t base = (size_t)i_glob * 512 + j0;

        if (tid < 128) srow[tid] = 0.f;
        if (tid < 64)  sslot[tid] = g_map[base + tid] - 1;
        for (int x = tid*4; x < 4096; x += 1024) {
            float4 v = *(const float4*)&g_SS[base*64 + x];
            *(float4*)&sA[(x >> 6)*68 + (x & 63)] = v;
        }
        __syncthreads();

        ull accp[4][4];
#pragma unroll
        for (int i = 0; i < 4; i++)
#pragma unroll
            for (int u = 0; u < 4; u++) accp[i][u] = 0ull;

#pragma unroll 16
        for (int k = 0; k < 64; k++) {
            ulonglong2 b0 = *(const ulonglong2*)&sB[k*128 + tx*8];
            ulonglong2 b1 = *(const ulonglong2*)&sB[k*128 + tx*8 + 4];
#pragma unroll
            for (int i = 0; i < 4; i++) {
                float av = sA[(ty*4 + i)*68 + k];
                ull ap; PACK2(ap, av, av);
                FMA2(accp[i][0], ap, b0.x, accp[i][0]);
                FMA2(accp[i][1], ap, b0.y, accp[i][1]);
                FMA2(accp[i][2], ap, b1.x, accp[i][2]);
                FMA2(accp[i][3], ap, b1.y, accp[i][3]);
            }
        }

        float add[8];
        {
            float4 u0a = *(const float4*)&g_u0[tx*8];
            float4 u0b = *(const float4*)&g_u0[tx*8 + 4];
            float4 aa  = *(const float4*)&g_atab[i_glob*128 + tx*8];
            float4 ab  = *(const float4*)&g_atab[i_glob*128 + tx*8 + 4];
            add[0]=u0a.x+aa.x; add[1]=u0a.y+aa.y; add[2]=u0a.z+aa.z; add[3]=u0a.w+aa.w;
            add[4]=u0b.x+ab.x; add[5]=u0b.y+ab.y; add[6]=u0b.z+ab.z; add[7]=u0b.w+ab.w;
        }

        float rsum[8];
#pragma unroll
        for (int u = 0; u < 8; u++) rsum[u] = 0.f;

#pragma unroll
        for (int i = 0; i < 4; i++) {
            int r = ty*4 + i;
            int j = j0 + r;
            float4 b0 = *(const float4*)&g_btab[j*128 + tx*8];
            float4 b1 = *(const float4*)&g_btab[j*128 + tx*8 + 4];
            float zb[8] = {b0.x, b0.y, b0.z, b0.w, b1.x, b1.y, b1.z, b1.w};
            int slot = sslot[r];
            if (slot >= 0) {
                float4 t0 = *(const float4*)&g_Ztc[(size_t)slot*128 + tx*8];
                float4 t1 = *(const float4*)&g_Ztc[(size_t)slot*128 + tx*8 + 4];
                zb[0]+=t0.x; zb[1]+=t0.y; zb[2]+=t0.z; zb[3]+=t0.w;
                zb[4]+=t1.x; zb[5]+=t1.y; zb[6]+=t1.z; zb[7]+=t1.w;
            }
            float acc[8];
#pragma unroll
            for (int u = 0; u < 4; u++) {
                float lo, hi; UNPACK2(lo, hi, accp[i][u]);
                acc[u*2] = lo; acc[u*2+1] = hi;
            }
            float hv[8];
#pragma unroll
            for (int u = 0; u < 8; u++) {
                hv[u] = siluf(acc[u] + add[u] + zb[u]);
                rsum[u] += hv[u];
                colsum[i][u] += hv[u];
            }
            if (j == i_glob) {
                *(float4*)&g_Hdiag[i_glob*128 + tx*8]     = make_float4(hv[0], hv[1], hv[2], hv[3]);
                *(float4*)&g_Hdiag[i_glob*128 + tx*8 + 4] = make_float4(hv[4], hv[5], hv[6], hv[7]);
            }
        }
#pragma unroll
        for (int u = 0; u < 8; u++) atomicAdd(&srow[tx*8 + u], rsum[u]);
        __syncthreads();
        if (tid < 32)
            red4(&g_sb.Hrow[i_glob*128 + tid*4],
                 srow[tid*4], srow[tid*4+1], srow[tid*4+2], srow[tid*4+3]);
        __syncthreads();
    }

    // flush column sums once (halved RED traffic vs per-i flush)
#pragma unroll
    for (int i = 0; i < 4; i++) {
        int j = j0 + ty*4 + i;
        red4(&g_sb.Hcol[j*128 + tx*8],     colsum[i][0], colsum[i][1], colsum[i][2], colsum[i][3]);
        red4(&g_sb.Hcol[j*128 + tx*8 + 4], colsum[i][4], colsum[i][5], colsum[i][6], colsum[i][7]);
    }
}

// ---------------- 11. apply W2 to aggregates ----------------
__global__ void k_ign(const float* __restrict__ w2, const float* __restrict__ b2)
{
    __shared__ float hd[128], hr[128], hc[128];
    int e = blockIdx.x, t = threadIdx.x;  // 128 threads, 513 blocks
    if (e < 512) {
        hd[t] = g_Hdiag[e*128 + t];
        hr[t] = g_sb.Hrow[e*128 + t];
        hc[t] = g_sb.Hcol[e*128 + t];
        __syncthreads();
        if (t < 64) {
            float d = 0.f, r = 0.f, c = 0.f;
#pragma unroll 8
            for (int k = 0; k < 128; k++) {
                float w = w2[k*64 + t];
                d += hd[k]*w; r += hr[k]*w; c += hc[k]*w;
            }
            float bb = b2[t];
            g_diag[e*64 + t] = d + bb;
            g_row[e*64 + t]  = r + 512.f*bb;
            g_col[e*64 + t]  = c + 512.f*bb;
        }
    } else {
        float st = 0.f, sr = 0.f;
        for (int i = 0; i < 512; i++) { st += g_sb.Hrow[i*128 + t]; sr += g_Hdiag[i*128 + t]; }
        hd[t] = st; hr[t] = sr;
        __syncthreads();
        if (t < 64) {
            float a = 0.f, b = 0.f;
#pragma unroll 8
            for (int k = 0; k < 128; k++) { float w = w2[k*64 + t]; a += hd[k]*w; b += hr[k]*w; }
            g_tot[t] = a + 262144.f*b2[t];
            g_tr[t]  = b + 512.f*b2[t];
        }
    }
}

// ---------------- 12. IGN linear + coord weights + segment scatter (fused) ----------------
__global__ void k_coord(const int* __restrict__ edges,
                        const float* __restrict__ ign_w, const float* __restrict__ ign_b,
                        const float* __restrict__ cw1, const float* __restrict__ cb1,
                        const float* __restrict__ cw2)
{
    __shared__ float feat[320];
    __shared__ float nb[64];
    __shared__ float red[128];
    int e = blockIdx.x, t = threadIdx.x;   // 128
    if (t < 64) {
        feat[t]       = g_diag[e*64 + t];
        feat[64 + t]  = g_row[e*64 + t];
        feat[128 + t] = g_col[e*64 + t];
        feat[192 + t] = g_tot[t];
        feat[256 + t] = g_tr[t];
    }
    __syncthreads();
    if (t < 64) {
        float o = ign_b[t];
#pragma unroll 8
        for (int k = 0; k < 320; k++) o += feat[k] * ign_w[k*64 + t];
        nb[t] = o;
    }
    __syncthreads();
    float acc = cb1[t];
#pragma unroll 8
    for (int k = 0; k < 64; k++) acc += nb[k] * cw1[k*128 + t];
    red[t] = siluf(acc) * cw2[t];
    __syncthreads();
    for (int st = 64; st > 0; st >>= 1) {
        if (t < st) red[t] += red[t + st];
        __syncthreads();
    }
    float w = red[0];
    int r = edges[e];
    if (t < 3)  atomicAdd(&g_sb.segx[r*3 + t], g_cdiff[e*3 + t] * w);
    if (t == 3) atomicAdd(&g_sb.cnt[r], 1.f);
    if (t >= 64) atomicAdd(&g_sb.nbt0[r*64 + (t - 64)], nb[t - 64]);
}

// ---------------- 13. node update + coord finalize + edge_attr copy (fused) ----------------
__global__ void k_node(const float* __restrict__ h, const float* __restrict__ x,
                       const float* __restrict__ nw1, const float* __restrict__ nb1,
                       const float* __restrict__ nw2, const float* __restrict__ nb2,
                       const float* __restrict__ ea, float* __restrict__ out)
{
    __shared__ float a[64];
    __shared__ float hid[128];
    int n = blockIdx.x, t = threadIdx.x;   // 128
    if (n >= NN) {   // edge_attr copy: blocks NN..NN+15 cover 2048 floats
        int i = (n - NN)*128 + t;
        out[NN*64 + NN*3 + i] = ea[i];
        return;
    }
    if (t < 64) a[t] = g_sb.nbt0[n*64 + t];
    __syncthreads();
    float acc = nb1[t];
#pragma unroll 8
    for (int k = 0; k < 64; k++) acc += a[k] * nw1[k*128 + t];
    hid[t] = siluf(acc);
    __syncthreads();
    if (t < 64) {
        float o = nb2[t];
#pragma unroll 8
        for (int k = 0; k < 128; k++) o += hid[k] * nw2[k*64 + t];
        out[n*64 + t] = h[n*64 + t] + o;
    } else if (t < 67) {
        int d = t - 64;
        float c = g_sb.cnt[n];
        if (c < 1.f) c = 1.f;
        out[NN*64 + n*3 + d] = x[n*3 + d] + g_sb.segx[n*3 + d] / c;
    }
}

// ---------------- host ----------------
extern "C" void kernel_launch(void* const* d_in, const int* in_sizes, int n_in,
                              void* d_out, int out_size)
{
    const float* h     = (const float*)d_in[0];
    const float* x     = (const float*)d_in[1];
    const int*   edges = (const int*)d_in[2];
    const int*   nbe   = (const int*)d_in[3];
    const float* ea    = (const float*)d_in[4];
    int wb = n_in - 25;
    const float* ew1  = (const float*)d_in[wb + 0];
    const float* eb1  = (const float*)d_in[wb + 1];
    const float* ew2  = (const float*)d_in[wb + 2];
    const float* eb2  = (const float*)d_in[wb + 3];
    const float* p1w1 = (const float*)d_in[wb + 4];
    const float* p1b1 = (const float*)d_in[wb + 5];
    const float* p1w2 = (const float*)d_in[wb + 6];
    const float* p1b2 = (const float*)d_in[wb + 7];
    const float* p2w1 = (const float*)d_in[wb + 8];
    const float* p2b1 = (const float*)d_in[wb + 9];
    const float* p2w2 = (const float*)d_in[wb + 10];
    const float* p2b2 = (const float*)d_in[wb + 11];
    const float* p3w1 = (const float*)d_in[wb + 12];
    const float* p3b1 = (const float*)d_in[wb + 13];
    const float* p3w2 = (const float*)d_in[wb + 14];
    const float* p3b2 = (const float*)d_in[wb + 15];
    const float* ignw = (const float*)d_in[wb + 16];
    const float* ignb = (const float*)d_in[wb + 17];
    const float* cw1  = (const float*)d_in[wb + 18];
    const float* cb1  = (const float*)d_in[wb + 19];
    const float* cw2  = (const float*)d_in[wb + 20];
    const float* ndw1 = (const float*)d_in[wb + 21];
    const float* ndb1 = (const float*)d_in[wb + 22];
    const float* ndw2 = (const float*)d_in[wb + 23];
    const float* ndb2 = (const float*)d_in[wb + 24];
    float* out = (float*)d_out;

    int smlp_smem  = (8192 + 64*96 + 32*128) * 4;        // 72 KB
    int fused_smem = (64*68 + 8192 + 128 + 64) * 4;
    cudaFuncSetAttribute(k_smlp,  cudaFuncAttributeMaxDynamicSharedMemorySize, smlp_smem);
    cudaFuncSetAttribute(k_fused, cudaFuncAttributeMaxDynamicSharedMemorySize, fused_smem);

    void* p;
    cudaGetSymbolAddress(&p, g_map);  cudaMemsetAsync(p, 0, sizeof(int)*RTOT, 0);
    cudaGetSymbolAddress(&p, g_nnz);  cudaMemsetAsync(p, 0, sizeof(int), 0);
    cudaGetSymbolAddress(&p, g_Tval); cudaMemsetAsync(p, 0, sizeof(float)*(size_t)SMAX*96, 0);
    cudaGetSymbolAddress(&p, g_SS);   cudaMemsetAsync(p, 0, sizeof(float)*(size_t)RTOT*64, 0);
    cudaGetSymbolAddress(&p, g_sb);   cudaMemsetAsync(p, 0, sizeof(SmallBufs), 0);

    k_edge<<<EE + 1, 128>>>(h, x, edges, ew1, eb1, ew2, eb2,
                            p1b1, p1w2, p1b2, p2b1, p2w2, p2b2);
    k_flag<<<MM/256, 256>>>(nbe);
    k_compact<<<RTOT/256, 256>>>();
    k_scat<<<MM, 128>>>(nbe);
    k_smlp<<<SMAX/64, 256, smlp_smem>>>(p1w1, p1b1, p1w2, p1b2,
                                        p2w1, p2b1, p2w2, p2b2);
    k_ab<<<1025, 128>>>(p3w1, p3b1);
    k_tc<<<SMAX, 128>>>(p3w1);
    k_cnt<<<SMAX/256, 256>>>();
    k_scan<<<1, 512>>>();
    k_fill<<<SMAX/256, 256>>>();
    k_ss<<<dim3(EE, 2), 256>>>();
    k_fused<<<RTOT/128, 256, fused_smem>>>(p3w1);
    k_ign<<<513, 128>>>(p3w2, p3b2);
    k_coord<<<EE, 128>>>(edges, ignw, ignb, cw1, cb1, cw2);
    k_node<<<NN + 16, 128>>>(h, x, ndw1, ndb1, ndw2, ndb2, ea, out);
}

// round 16
// speedup vs baseline: 1.0449x; 1.0449x over previous
#include <cuda_runtime.h>
#include <math.h>

#define NN 512
#define EE 512
#define MM 16384
#define FINW 64
#define RTOT (EE*EE)   // 262144
#define SMAX 16384

typedef unsigned long long ull;

// packed f32x2 helpers (sm_90+/sm_103a PTX; FFMA2 in SASS)
#define PACK2(d, lo, hi) asm("mov.b64 %0, {%1,%2};" : "=l"(d) : "f"(lo), "f"(hi))
#define UNPACK2(lo, hi, s) asm("mov.b64 {%0,%1}, %2;" : "=f"(lo), "=f"(hi) : "l"(s))
#define FMA2(d, a, b, c) asm("fma.rn.f32x2 %0, %1, %2, %3;" : "=l"(d) : "l"(a), "l"(b), "l"(c))

// ---------------- scratch (device globals) ----------------
struct SmallBufs {          // zeroed with ONE memset
    float rowS1[EE*64];
    float colS2[EE*64];
    float Hrow[EE*128];
    float Hcol[EE*128];
    float segx[NN*3];
    float cnt[NN];
    float nbt0[NN*FINW];
    int   cntA[EE];
    int   cntB[EE];
};
__device__ SmallBufs g_sb;

__device__ float g_efn[EE*FINW];
__device__ float g_cdiff[EE*3];
__device__ int   g_map[RTOT];          // 0 = empty, else slot+1
__device__ int   g_cells[SMAX];
__device__ int   g_nnz;
__device__ float g_Tval[(size_t)SMAX*96];
__device__ float g_S1[(size_t)SMAX*64];
__device__ float g_S2[(size_t)SMAX*64];
__device__ float g_c1[64], g_c2[64], g_u0[128];
__device__ float g_atab[EE*128], g_btab[EE*128];
__device__ int   g_offA[EE], g_offB[EE], g_curA[EE], g_curB[EE];
__device__ int   g_listA[SMAX], g_listB[SMAX];
__device__ float g_SS[(size_t)RTOT*64];     // 64 MB
__device__ float g_Ztc[(size_t)SMAX*128];   // 8 MB
__device__ float g_Hdiag[EE*128];
__device__ float g_diag[EE*FINW], g_row[EE*FINW], g_col[EE*FINW];
__device__ float g_tot[FINW], g_tr[FINW];

__device__ __forceinline__ float siluf(float v) {
    return v * __fdividef(1.f, 1.f + __expf(-v));
}

// vector fp32 reduction (sm_90+): one instruction, 16B payload
__device__ __forceinline__ void red4(float* addr, float a, float b, float c, float d) {
    asm volatile("red.global.add.v4.f32 [%0], {%1,%2,%3,%4};"
                 :: "l"(addr), "f"(a), "f"(b), "f"(c), "f"(d) : "memory");
}

// ---------------- 1. edge encoder + coord_diff (+ c1/c2 constants in last block) ----------------
__global__ void k_edge(const float* __restrict__ h, const float* __restrict__ x,
                       const int* __restrict__ edges,
                       const float* __restrict__ ew1, const float* __restrict__ eb1,
                       const float* __restrict__ ew2, const float* __restrict__ eb2,
                       const float* __restrict__ p1b1, const float* __restrict__ p1w2,
                       const float* __restrict__ p1b2,
                       const float* __restrict__ p2b1, const float* __restrict__ p2w2,
                       const float* __restrict__ p2b2)
{
    __shared__ float hcat[128];
    __shared__ float hid[128];
    int e = blockIdx.x, t = threadIdx.x;
    if (e == EE) {   // c1/c2 constants
        hcat[t] = siluf(p1b1[t]);
        hid[t]  = siluf(p2b1[t]);
        __syncthreads();
        if (t < 64) {
            float a = p1b2[t], b = p2b2[t];
#pragma unroll 8
            for (int k = 0; k < 128; k++) { a += hcat[k]*p1w2[k*64+t]; b += hid[k]*p2w2[k*64+t]; }
            g_c1[t] = a; g_c2[t] = b;
        }
        return;
    }
    int r = edges[e], c = edges[EE + e];
    if (t < 64) hcat[t] = h[r*64 + t];
    else        hcat[t] = h[c*64 + (t - 64)];
    if (t < 3)  g_cdiff[e*3 + t] = x[r*3 + t] - x[c*3 + t];
    __syncthreads();
    float acc = eb1[t];
#pragma unroll 8
    for (int k = 0; k < 128; k++) acc += hcat[k] * ew1[k*128 + t];
    hid[t] = siluf(acc);
    __syncthreads();
    if (t < 64) {
        float o = eb2[t];
#pragma unroll 8
        for (int k = 0; k < 128; k++) o += hid[k] * ew2[k*64 + t];
        g_efn[e*64 + t] = o;
    }
}

// ---------------- 2. occupancy flag + compaction ----------------
__global__ void k_flag(const int* __restrict__ nbe)
{
    int m = blockIdx.x * blockDim.x + threadIdx.x;
    if (m < MM) g_map[nbe[m]*EE + nbe[MM + m]] = 1;
}

__global__ void k_compact()
{
    int cell = blockIdx.x * blockDim.x + threadIdx.x;
    if (cell < RTOT && g_map[cell] != 0) {
        int slot = atomicAdd(&g_nnz, 1);
        g_map[cell] = slot + 1;
        g_cells[slot] = cell;
    }
}

// ---------------- 3. VTV + PE + scatter into compact T ----------------
__global__ void k_scat(const int* __restrict__ nbe)
{
    int m = blockIdx.x, f = threadIdx.x;  // 128 threads, 96 active
    if (f >= 96) return;
    int a = nbe[m], b = nbe[MM + m];
    float val;
    if (f < 32) {
        float vtv = 0.f;
#pragma unroll
        for (int d = 0; d < 3; d++) vtv += g_cdiff[a*3 + d] * g_cdiff[b*3 + d];
        int i = f >> 1;
        float ang = vtv * 16.f * expf(-0.5756462732485115f * (float)i);
        val = (f & 1) ? cosf(ang) : sinf(ang);
    } else {
        val = g_efn[a*64 + (f - 32)] * g_efn[b*64 + (f - 32)];
    }
    int slot = g_map[a*EE + b] - 1;
    atomicAdd(&g_Tval[(size_t)slot*96 + f], val);
}

// ---------------- fused 2-layer MLP, W2 overlaid on sA+W1 region ----------------
template<int K1>
__device__ __forceinline__ void mlp_tile(float* region, float* sHid,
    const float* __restrict__ W1, const float* __restrict__ b1,
    const float* __restrict__ W2, const float* __restrict__ b2,
    float acc2[4][4])
{
    float* sA  = region;
    float* sW1 = region + 64*K1;
    int tid = threadIdx.x, ty = tid >> 4, tx = tid & 15;
    ull accp[4][4];
#pragma unroll
    for (int i = 0; i < 4; i++)
#pragma unroll
        for (int u = 0; u < 4; u++) accp[i][u] = 0ull;

    for (int kc = 0; kc < K1; kc += 32) {
        for (int i = tid*4; i < 32*128; i += 1024)
            *(float4*)&sW1[i] = *(const float4*)&W1[kc*128 + i];
        __syncthreads();
#pragma unroll 8
        for (int k = 0; k < 32; k++) {
            ulonglong2 b0 = *(const ulonglong2*)&sW1[k*128 + tx*8];
            ulonglong2 b1v = *(const ulonglong2*)&sW1[k*128 + tx*8 + 4];
#pragma unroll
            for (int i = 0; i < 4; i++) {
                float av = sA[(ty*4 + i)*K1 + kc + k];
                ull ap; PACK2(ap, av, av);
                FMA2(accp[i][0], ap, b0.x, accp[i][0]);
                FMA2(accp[i][1], ap, b0.y, accp[i][1]);
                FMA2(accp[i][2], ap, b1v.x, accp[i][2]);
                FMA2(accp[i][3], ap, b1v.y, accp[i][3]);
            }
        }
        __syncthreads();
    }
#pragma unroll
    for (int i = 0; i < 4; i++)
#pragma unroll
        for (int u = 0; u < 4; u++) {
            float lo, hi; UNPACK2(lo, hi, accp[i][u]);
            int j = tx*8 + u*2;
            sHid[(ty*4 + i)*128 + j]     = siluf(lo + b1[j]);
            sHid[(ty*4 + i)*128 + j + 1] = siluf(hi + b1[j + 1]);
        }
    __syncthreads();
    for (int i = tid*4; i < 128*64; i += 1024)
        *(float4*)&region[i] = *(const float4*)&W2[i];
    __syncthreads();

    ull acc2p[4][2];
#pragma unroll
    for (int i = 0; i < 4; i++) { acc2p[i][0] = 0ull; acc2p[i][1] = 0ull; }
#pragma unroll 8
    for (int k = 0; k < 128; k++) {
        ulonglong2 b = *(const ulonglong2*)&region[k*64 + tx*4];
#pragma unroll
        for (int i = 0; i < 4; i++) {
            float av = sHid[(ty*4 + i)*128 + k];
            ull ap; PACK2(ap, av, av);
            FMA2(acc2p[i][0], ap, b.x, acc2p[i][0]);
            FMA2(acc2p[i][1], ap, b.y, acc2p[i][1]);
        }
    }
#pragma unroll
    for (int i = 0; i < 4; i++) {
        float lo, hi;
        UNPACK2(lo, hi, acc2p[i][0]);
        acc2[i][0] = lo + b2[tx*4];     acc2[i][1] = hi + b2[tx*4 + 1];
        UNPACK2(lo, hi, acc2p[i][1]);
        acc2[i][2] = lo + b2[tx*4 + 2]; acc2[i][3] = hi + b2[tx*4 + 3];
    }
    __syncthreads();
}

// ---------------- 5. sparse MLPs: S1,S2 + row/col sums (v4 REDs) ----------------
__global__ void __launch_bounds__(256, 3) k_smlp(
    const float* __restrict__ p1w1, const float* __restrict__ p1b1,
    const float* __restrict__ p1w2, const float* __restrict__ p1b2,
    const float* __restrict__ p2w1, const float* __restrict__ p2b1,
    const float* __restrict__ p2w2, const float* __restrict__ p2b2)
{
    extern __shared__ float smem[];
    float* sHid   = smem;            // 8192
    float* region = smem + 8192;     // 64*96 + 32*128 = 10240
    int base = blockIdx.x * 64;
    int tid = threadIdx.x, ty = tid >> 4, tx = tid & 15;
    int nnz = g_nnz;

    const float* Tp = &g_Tval[(size_t)base * 96];
    for (int i = tid*4; i < 64*96; i += 1024)
        *(float4*)&region[i] = *(const float4*)&Tp[i];
    __syncthreads();

    float4 c1v = *(const float4*)&g_c1[tx*4];
    float4 c2v = *(const float4*)&g_c2[tx*4];

    float acc2[4][4];
    mlp_tile<96>(region, sHid, p1w1, p1b1, p1w2, p1b2, acc2);
#pragma unroll
    for (int i = 0; i < 4; i++) {
        int slot = base + ty*4 + i;
        if (slot < nnz) {
            int cell = g_cells[slot];
            float v0 = acc2[i][0] - c1v.x, v1 = acc2[i][1] - c1v.y;
            float v2 = acc2[i][2] - c1v.z, v3 = acc2[i][3] - c1v.w;
            *(float4*)&g_S1[(size_t)slot*64 + tx*4] = make_float4(v0, v1, v2, v3);
            red4(&g_sb.rowS1[(cell >> 9)*64 + tx*4], v0, v1, v2, v3);
        }
    }
    __syncthreads();
    for (int i = tid*4; i < 64*96; i += 1024)
        *(float4*)&region[i] = *(const float4*)&Tp[i];
    __syncthreads();

    mlp_tile<96>(region, sHid, p2w1, p2b1, p2w2, p2b2, acc2);
#pragma unroll
    for (int i = 0; i < 4; i++) {
        int slot = base + ty*4 + i;
        if (slot < nnz) {
            int cell = g_cells[slot];
            float v0 = acc2[i][0] - c2v.x, v1 = acc2[i][1] - c2v.y;
            float v2 = acc2[i][2] - c2v.z, v3 = acc2[i][3] - c2v.w;
            *(float4*)&g_S2[(size_t)slot*64 + tx*4] = make_float4(v0, v1, v2, v3);
            red4(&g_sb.colS2[(cell & 511)*64 + tx*4], v0, v1, v2, v3);
        }
    }
}

// ---------------- 6. a_i / b_j tables (+ u0 in last block) ----------------
__global__ void k_ab(const float* __restrict__ p3w1, const float* __restrict__ p3b1)
{
    __shared__ float r[64];
    int b = blockIdx.x, t = threadIdx.x;  // 128
    if (b < 512) {
        int i = b;
        if (t < 64) r[t] = g_sb.rowS1[i*64 + t] * g_c2[t];
        __syncthreads();
        float a = 0.f;
#pragma unroll 8
        for (int f = 0; f < 64; f++) a += r[f] * p3w1[(96+f)*128 + t];
        g_atab[i*128 + t] = a;
    } else if (b < 1024) {
        int j = b - 512;
        if (t < 64) r[t] = g_sb.colS2[j*64 + t] * g_c1[t];
        __syncthreads();
        float a = 0.f;
#pragma unroll 8
        for (int f = 0; f < 64; f++) a += r[f] * p3w1[(96+f)*128 + t];
        g_btab[j*128 + t] = a;
    } else {
        if (t < 64) r[t] = 512.f * g_c1[t] * g_c2[t];
        __syncthreads();
        float u = p3b1[t];
#pragma unroll 8
        for (int f = 0; f < 64; f++) u += r[f] * p3w1[(96+f)*128 + t];
        g_u0[t] = u;
    }
}

// ---------------- 7. group slots by middle index ----------------
__global__ void k_cnt()
{
    int s = blockIdx.x * blockDim.x + threadIdx.x;
    if (s < g_nnz) {
        int cell = g_cells[s];
        atomicAdd(&g_sb.cntA[cell & 511], 1);
        atomicAdd(&g_sb.cntB[cell >> 9], 1);
    }
}

__global__ void k_scan()
{
    __shared__ int s[512];
    int t = threadIdx.x;  // 512
    s[t] = g_sb.cntA[t]; __syncthreads();
    for (int d = 1; d < 512; d <<= 1) {
        int v = (t >= d) ? s[t - d] : 0;
        __syncthreads();
        s[t] += v;
        __syncthreads();
    }
    int exc = s[t] - g_sb.cntA[t];
    g_offA[t] = exc; g_curA[t] = exc;
    __syncthreads();
    s[t] = g_sb.cntB[t]; __syncthreads();
    for (int d = 1; d < 512; d <<= 1) {
        int v = (t >= d) ? s[t - d] : 0;
        __syncthreads();
        s[t] += v;
        __syncthreads();
    }
    exc = s[t] - g_sb.cntB[t];
    g_offB[t] = exc; g_curB[t] = exc;
}

__global__ void k_fill()
{
    int s = blockIdx.x * blockDim.x + threadIdx.x;
    if (s < g_nnz) {
        int cell = g_cells[s];
        int pa = atomicAdd(&g_curA[cell & 511], 1);
        g_listA[pa] = s;
        int pb = atomicAdd(&g_curB[cell >> 9], 1);
        g_listB[pb] = s;
    }
}

// ---------------- 8. sparse-sparse product, f-split (grid 512 x 2) ----------------
__global__ void __launch_bounds__(256) k_ss()
{
    __shared__ float sA[64*32];
    __shared__ float sB[64*32];
    __shared__ int ri[64], cj[64];
    int k = blockIdx.x, tid = threadIdx.x;
    int f0 = blockIdx.y * 32;
    int cA = g_sb.cntA[k], cB = g_sb.cntB[k];
    if (cA == 0 || cB == 0) return;
    int oA = g_offA[k], oB = g_offB[k];

    for (int a0 = 0; a0 < cA; a0 += 64) {
        int nA = min(64, cA - a0);
        __syncthreads();
        for (int x = tid; x < nA*32; x += 256) {
            int r = x >> 5;
            int slot = g_listA[oA + a0 + r];
            sA[x] = g_S1[(size_t)slot*64 + f0 + (x & 31)];
        }
        for (int r = tid; r < nA; r += 256) ri[r] = g_cells[g_listA[oA + a0 + r]] >> 9;
        for (int b0 = 0; b0 < cB; b0 += 64) {
            int nB = min(64, cB - b0);
            __syncthreads();
            for (int x = tid; x < nB*32; x += 256) {
                int c = x >> 5;
                int slot = g_listB[oB + b0 + c];
                sB[x] = g_S2[(size_t)slot*64 + f0 + (x & 31)];
            }
            for (int c = tid; c < nB; c += 256) cj[c] = g_cells[g_listB[oB + b0 + c]] & 511;
            __syncthreads();
            int fg = tid & 7, pc = tid >> 3;
            for (int r = 0; r < nA; r++) {
                float4 av = *(const float4*)&sA[r*32 + fg*4];
                int ibase = ri[r];
                for (int c = pc; c < nB; c += 32) {
                    float4 bv = *(const float4*)&sB[c*32 + fg*4];
                    red4(&g_SS[((size_t)ibase*512 + cj[c])*64 + f0 + fg*4],
                         av.x*bv.x, av.y*bv.y, av.z*bv.z, av.w*bv.w);
                }
            }
        }
    }
}

// ---------------- 9. Ztc[slot] = W1t^T Tval[slot] ----------------
__global__ void k_tc(const float* __restrict__ p3w1)
{
    __shared__ float tv[96];
    int slot = blockIdx.x, t = threadIdx.x;  // 128
    if (slot >= g_nnz) return;
    if (t < 96) tv[t] = g_Tval[(size_t)slot*96 + t];
    __syncthreads();
    float acc = 0.f;
#pragma unroll 8
    for (int k = 0; k < 96; k++) acc += tv[k] * p3w1[k*128 + t];
    g_Ztc[(size_t)slot*128 + t] = acc;
}

// ---------------- 10. FUSED: Z-GEMM (f32x2, float4 A-loads) + SiLU + reductions ----------------
__global__ void __launch_bounds__(256) k_fused(const float* __restrict__ p3w1)
{
    extern __shared__ float dsm[];
    float* sA   = dsm;                  // [64][68]
    float* sB   = sA + 64*68;           // [64][128]  W1m
    float* srow = sB + 8192;            // [128]
    int*  sslot = (int*)(srow + 128);   // [64]

    size_t base = (size_t)blockIdx.x * 64;
    int i_glob = (int)(base >> 9);
    int j0 = (int)(base & 511);
    int tid = threadIdx.x;

    for (int x = tid*4; x < 4096; x += 1024) {
        float4 v = *(const float4*)&g_SS[base*64 + x];
        int cell = x >> 6, k = x & 63;
        *(float4*)&sA[cell*68 + k] = v;
    }
    for (int x = tid*4; x < 8192; x += 1024)
        *(float4*)&sB[x] = *(const float4*)&p3w1[96*128 + x];
    if (tid < 128) srow[tid] = 0.f;
    if (tid < 64)  sslot[tid] = g_map[base + tid] - 1;
    __syncthreads();

    int ty = tid >> 4, tx = tid & 15;
    ull accp[4][4];
#pragma unroll
    for (int i = 0; i < 4; i++)
#pragma unroll
        for (int u = 0; u < 4; u++) accp[i][u] = 0ull;

#pragma unroll
    for (int k4 = 0; k4 < 64; k4 += 4) {
        float4 a4[4];
#pragma unroll
        for (int i = 0; i < 4; i++)
            a4[i] = *(const float4*)&sA[(ty*4 + i)*68 + k4];
#pragma unroll
        for (int kk = 0; kk < 4; kk++) {
            ulonglong2 b0 = *(const ulonglong2*)&sB[(k4+kk)*128 + tx*8];
            ulonglong2 b1 = *(const ulonglong2*)&sB[(k4+kk)*128 + tx*8 + 4];
#pragma unroll
            for (int i = 0; i < 4; i++) {
                float av = ((const float*)&a4[i])[kk];
                ull ap; PACK2(ap, av, av);
                FMA2(accp[i][0], ap, b0.x, accp[i][0]);
                FMA2(accp[i][1], ap, b0.y, accp[i][1]);
                FMA2(accp[i][2], ap, b1.x, accp[i][2]);
                FMA2(accp[i][3], ap, b1.y, accp[i][3]);
            }
        }
    }

    float add[8];
    {
        float4 u0a = *(const float4*)&g_u0[tx*8];
        float4 u0b = *(const float4*)&g_u0[tx*8 + 4];
        float4 aa  = *(const float4*)&g_atab[i_glob*128 + tx*8];
        float4 ab  = *(const float4*)&g_atab[i_glob*128 + tx*8 + 4];
        add[0]=u0a.x+aa.x; add[1]=u0a.y+aa.y; add[2]=u0a.z+aa.z; add[3]=u0a.w+aa.w;
        add[4]=u0b.x+ab.x; add[5]=u0b.y+ab.y; add[6]=u0b.z+ab.z; add[7]=u0b.w+ab.w;
    }

    float rsum[8];
#pragma unroll
    for (int u = 0; u < 8; u++) rsum[u] = 0.f;

#pragma unroll
    for (int i = 0; i < 4; i++) {
        int r = ty*4 + i;
        int j = j0 + r;
        float4 b0 = *(const float4*)&g_btab[j*128 + tx*8];
        float4 b1 = *(const float4*)&g_btab[j*128 + tx*8 + 4];
        float zb[8] = {b0.x, b0.y, b0.z, b0.w, b1.x, b1.y, b1.z, b1.w};
        int slot = sslot[r];
        if (slot >= 0) {
            float4 t0 = *(const float4*)&g_Ztc[(size_t)slot*128 + tx*8];
            float4 t1 = *(const float4*)&g_Ztc[(size_t)slot*128 + tx*8 + 4];
            zb[0]+=t0.x; zb[1]+=t0.y; zb[2]+=t0.z; zb[3]+=t0.w;
            zb[4]+=t1.x; zb[5]+=t1.y; zb[6]+=t1.z; zb[7]+=t1.w;
        }
        float acc[8];
#pragma unroll
        for (int u = 0; u < 4; u++) {
            float lo, hi; UNPACK2(lo, hi, accp[i][u]);
            acc[u*2] = lo; acc[u*2+1] = hi;
        }
        float hv[8];
#pragma unroll
        for (int u = 0; u < 8; u++) {
            hv[u] = siluf(acc[u] + add[u] + zb[u]);
            rsum[u] += hv[u];
        }
        if (j == i_glob) {
            *(float4*)&g_Hdiag[i_glob*128 + tx*8]     = make_float4(hv[0], hv[1], hv[2], hv[3]);
            *(float4*)&g_Hdiag[i_glob*128 + tx*8 + 4] = make_float4(hv[4], hv[5], hv[6], hv[7]);
        }
        red4(&g_sb.Hcol[j*128 + tx*8],     hv[0], hv[1], hv[2], hv[3]);
        red4(&g_sb.Hcol[j*128 + tx*8 + 4], hv[4], hv[5], hv[6], hv[7]);
    }
#pragma unroll
    for (int u = 0; u < 8; u++) atomicAdd(&srow[tx*8 + u], rsum[u]);
    __syncthreads();
    if (tid < 32)
        red4(&g_sb.Hrow[i_glob*128 + tid*4],
             srow[tid*4], srow[tid*4+1], srow[tid*4+2], srow[tid*4+3]);
}

// ---------------- 11. apply W2 to aggregates ----------------
__global__ void k_ign(const float* __restrict__ w2, const float* __restrict__ b2)
{
    __shared__ float hd[128], hr[128], hc[128];
    int e = blockIdx.x, t = threadIdx.x;  // 128 threads, 513 blocks
    if (e < 512) {
        hd[t] = g_Hdiag[e*128 + t];
        hr[t] = g_sb.Hrow[e*128 + t];
        hc[t] = g_sb.Hcol[e*128 + t];
        __syncthreads();
        if (t < 64) {
            float d = 0.f, r = 0.f, c = 0.f;
#pragma unroll 8
            for (int k = 0; k < 128; k++) {
                float w = w2[k*64 + t];
                d += hd[k]*w; r += hr[k]*w; c += hc[k]*w;
            }
            float bb = b2[t];
            g_diag[e*64 + t] = d + bb;
            g_row[e*64 + t]  = r + 512.f*bb;
            g_col[e*64 + t]  = c + 512.f*bb;
        }
    } else {
        float st = 0.f, sr = 0.f;
        for (int i = 0; i < 512; i++) { st += g_sb.Hrow[i*128 + t]; sr += g_Hdiag[i*128 + t]; }
        hd[t] = st; hr[t] = sr;
        __syncthreads();
        if (t < 64) {
            float a = 0.f, b = 0.f;
#pragma unroll 8
            for (int k = 0; k < 128; k++) { float w = w2[k*64 + t]; a += hd[k]*w; b += hr[k]*w; }
            g_tot[t] = a + 262144.f*b2[t];
            g_tr[t]  = b + 512.f*b2[t];
        }
    }
}

// ---------------- 12. IGN linear + coord weights + segment scatter (fused) ----------------
__global__ void k_coord(const int* __restrict__ edges,
                        const float* __restrict__ ign_w, const float* __restrict__ ign_b,
                        const float* __restrict__ cw1, const float* __restrict__ cb1,
                        const float* __restrict__ cw2)
{
    __shared__ float feat[320];
    __shared__ float nb[64];
    __shared__ float red[128];
    int e = blockIdx.x, t = threadIdx.x;   // 128
    if (t < 64) {
        feat[t]       = g_diag[e*64 + t];
        feat[64 + t]  = g_row[e*64 + t];
        feat[128 + t] = g_col[e*64 + t];
        feat[192 + t] = g_tot[t];
        feat[256 + t] = g_tr[t];
    }
    __syncthreads();
    if (t < 64) {
        float o = ign_b[t];
#pragma unroll 8
        for (int k = 0; k < 320; k++) o += feat[k] * ign_w[k*64 + t];
        nb[t] = o;
    }
    __syncthreads();
    float acc = cb1[t];
#pragma unroll 8
    for (int k = 0; k < 64; k++) acc += nb[k] * cw1[k*128 + t];
    red[t] = siluf(acc) * cw2[t];
    __syncthreads();
    for (int st = 64; st > 0; st >>= 1) {
        if (t < st) red[t] += red[t + st];
        __syncthreads();
    }
    float w = red[0];
    int r = edges[e];
    if (t < 3)  atomicAdd(&g_sb.segx[r*3 + t], g_cdiff[e*3 + t] * w);
    if (t == 3) atomicAdd(&g_sb.cnt[r], 1.f);
    if (t >= 64) atomicAdd(&g_sb.nbt0[r*64 + (t - 64)], nb[t - 64]);
}

// ---------------- 13. node update + coord finalize + edge_attr copy (fused) ----------------
__global__ void k_node(const float* __restrict__ h, const float* __restrict__ x,
                       const float* __restrict__ nw1, const float* __restrict__ nb1,
                       const float* __restrict__ nw2, const float* __restrict__ nb2,
                       const float* __restrict__ ea, float* __restrict__ out)
{
    __shared__ float a[64];
    __shared__ float hid[128];
    int n = blockIdx.x, t = threadIdx.x;   // 128
    if (n >= NN) {   // edge_attr copy: blocks NN..NN+15 cover 2048 floats
        int i = (n - NN)*128 + t;
        out[NN*64 + NN*3 + i] = ea[i];
        return;
    }
    if (t < 64) a[t] = g_sb.nbt0[n*64 + t];
    __syncthreads();
    float acc = nb1[t];
#pragma unroll 8
    for (int k = 0; k < 64; k++) acc += a[k] * nw1[k*128 + t];
    hid[t] = siluf(acc);
    __syncthreads();
    if (t < 64) {
        float o = nb2[t];
#pragma unroll 8
        for (int k = 0; k < 128; k++) o += hid[k] * nw2[k*64 + t];
        out[n*64 + t] = h[n*64 + t] + o;
    } else if (t < 67) {
        int d = t - 64;
        float c = g_sb.cnt[n];
        if (c < 1.f) c = 1.f;
        out[NN*64 + n*3 + d] = x[n*3 + d] + g_sb.segx[n*3 + d] / c;
    }
}

// ---------------- host ----------------
extern "C" void kernel_launch(void* const* d_in, const int* in_sizes, int n_in,
                              void* d_out, int out_size)
{
    const float* h     = (const float*)d_in[0];
    const float* x     = (const float*)d_in[1];
    const int*   edges = (const int*)d_in[2];
    const int*   nbe   = (const int*)d_in[3];
    const float* ea    = (const float*)d_in[4];
    int wb = n_in - 25;
    const float* ew1  = (const float*)d_in[wb + 0];
    const float* eb1  = (const float*)d_in[wb + 1];
    const float* ew2  = (const float*)d_in[wb + 2];
    const float* eb2  = (const float*)d_in[wb + 3];
    const float* p1w1 = (const float*)d_in[wb + 4];
    const float* p1b1 = (const float*)d_in[wb + 5];
    const float* p1w2 = (const float*)d_in[wb + 6];
    const float* p1b2 = (const float*)d_in[wb + 7];
    const float* p2w1 = (const float*)d_in[wb + 8];
    const float* p2b1 = (const float*)d_in[wb + 9];
    const float* p2w2 = (const float*)d_in[wb + 10];
    const float* p2b2 = (const float*)d_in[wb + 11];
    const float* p3w1 = (const float*)d_in[wb + 12];
    const float* p3b1 = (const float*)d_in[wb + 13];
    const float* p3w2 = (const float*)d_in[wb + 14];
    const float* p3b2 = (const float*)d_in[wb + 15];
    const float* ignw = (const float*)d_in[wb + 16];
    const float* ignb = (const float*)d_in[wb + 17];
    const float* cw1  = (const float*)d_in[wb + 18];
    const float* cb1  = (const float*)d_in[wb + 19];
    const float* cw2  = (const float*)d_in[wb + 20];
    const float* ndw1 = (const float*)d_in[wb + 21];
    const float* ndb1 = (const float*)d_in[wb + 22];
    const float* ndw2 = (const float*)d_in[wb + 23];
    const float* ndb2 = (const float*)d_in[wb + 24];
    float* out = (float*)d_out;

    int smlp_smem  = (8192 + 64*96 + 32*128) * 4;        // 72 KB
    int fused_smem = (64*68 + 8192 + 128 + 64) * 4;
    cudaFuncSetAttribute(k_smlp,  cudaFuncAttributeMaxDynamicSharedMemorySize, smlp_smem);
    cudaFuncSetAttribute(k_fused, cudaFuncAttributeMaxDynamicSharedMemorySize, fused_smem);

    void* p;
    cudaGetSymbolAddress(&p, g_map);  cudaMemsetAsync(p, 0, sizeof(int)*RTOT, 0);
    cudaGetSymbolAddress(&p, g_nnz);  cudaMemsetAsync(p, 0, sizeof(int), 0);
    cudaGetSymbolAddress(&p, g_Tval); cudaMemsetAsync(p, 0, sizeof(float)*(size_t)SMAX*96, 0);
    cudaGetSymbolAddress(&p, g_SS);   cudaMemsetAsync(p, 0, sizeof(float)*(size_t)RTOT*64, 0);
    cudaGetSymbolAddress(&p, g_sb);   cudaMemsetAsync(p, 0, sizeof(SmallBufs), 0);

    k_edge<<<EE + 1, 128>>>(h, x, edges, ew1, eb1, ew2, eb2,
                            p1b1, p1w2, p1b2, p2b1, p2w2, p2b2);
    k_flag<<<MM/256, 256>>>(nbe);
    k_compact<<<RTOT/256, 256>>>();
    k_scat<<<MM, 128>>>(nbe);
    k_smlp<<<SMAX/64, 256, smlp_smem>>>(p1w1, p1b1, p1w2, p1b2,
                                        p2w1, p2b1, p2w2, p2b2);
    k_ab<<<1025, 128>>>(p3w1, p3b1);
    k_tc<<<SMAX, 128>>>(p3w1);
    k_cnt<<<SMAX/256, 256>>>();
    k_scan<<<1, 512>>>();
    k_fill<<<SMAX/256, 256>>>();
    k_ss<<<dim3(EE, 2), 256>>>();
    k_fused<<<RTOT/64, 256, fused_smem>>>(p3w1);
    k_ign<<<513, 128>>>(p3w2, p3b2);
    k_coord<<<EE, 128>>>(edges, ignw, ignb, cw1, cb1, cw2);
    k_node<<<NN + 16, 128>>>(h, x, ndw1, ndb1, ndw2, ndb2, ea, out);
}

// round 17
// speedup vs baseline: 1.0628x; 1.0171x over previous
#include <cuda_runtime.h>
#include <math.h>

#define NN 512
#define EE 512
#define MM 16384
#define FINW 64
#define RTOT (EE*EE)   // 262144
#define SMAX 16384

typedef unsigned long long ull;

// packed f32x2 helpers (sm_90+/sm_103a PTX; FFMA2 in SASS)
#define PACK2(d, lo, hi) asm("mov.b64 %0, {%1,%2};" : "=l"(d) : "f"(lo), "f"(hi))
#define UNPACK2(lo, hi, s) asm("mov.b64 {%0,%1}, %2;" : "=f"(lo), "=f"(hi) : "l"(s))
#define FMA2(d, a, b, c) asm("fma.rn.f32x2 %0, %1, %2, %3;" : "=l"(d) : "l"(a), "l"(b), "l"(c))

// ---------------- scratch (device globals) ----------------
struct SmallBufs {          // zeroed with ONE memset
    float rowS1[EE*64];
    float colS2[EE*64];
    float Hrow[EE*128];
    float Hcol[EE*128];
    float segx[NN*3];
    float cnt[NN];
    float nbt0[NN*FINW];
    int   cntA[EE];
    int   cntB[EE];
};
__device__ SmallBufs g_sb;

__device__ float g_efn[EE*FINW];
__device__ float g_cdiff[EE*3];
__device__ int   g_map[RTOT];          // 0 = empty, else slot+1
__device__ int   g_cells[SMAX];
__device__ int   g_nnz;
__device__ float g_Tval[(size_t)SMAX*96];
__device__ float g_S1[(size_t)SMAX*64];
__device__ float g_S2[(size_t)SMAX*64];
__device__ float g_c1[64], g_c2[64], g_u0[128];
__device__ float g_atab[EE*128], g_btab[EE*128];
__device__ int   g_offA[EE], g_offB[EE], g_curA[EE], g_curB[EE];
__device__ int   g_listA[SMAX], g_listB[SMAX];
__device__ float g_SS[(size_t)RTOT*64];     // 64 MB
__device__ float g_Ztc[(size_t)SMAX*128];   // 8 MB
__device__ float g_Hdiag[EE*128];
__device__ float g_diag[EE*FINW], g_row[EE*FINW], g_col[EE*FINW];
__device__ float g_tot[FINW], g_tr[FINW];

__device__ __forceinline__ float siluf(float v) {
    return v * __fdividef(1.f, 1.f + __expf(-v));
}

// vector fp32 reduction (sm_90+): one instruction, 16B payload
__device__ __forceinline__ void red4(float* addr, float a, float b, float c, float d) {
    asm volatile("red.global.add.v4.f32 [%0], {%1,%2,%3,%4};"
                 :: "l"(addr), "f"(a), "f"(b), "f"(c), "f"(d) : "memory");
}

// ---------------- 1. edge encoder + coord_diff (+ c1/c2 constants in last block) ----------------
__global__ void k_edge(const float* __restrict__ h, const float* __restrict__ x,
                       const int* __restrict__ edges,
                       const float* __restrict__ ew1, const float* __restrict__ eb1,
                       const float* __restrict__ ew2, const float* __restrict__ eb2,
                       const float* __restrict__ p1b1, const float* __restrict__ p1w2,
                       const float* __restrict__ p1b2,
                       const float* __restrict__ p2b1, const float* __restrict__ p2w2,
                       const float* __restrict__ p2b2)
{
    __shared__ float hcat[128];
    __shared__ float hid[128];
    int e = blockIdx.x, t = threadIdx.x;
    if (e == EE) {   // c1/c2 constants
        hcat[t] = siluf(p1b1[t]);
        hid[t]  = siluf(p2b1[t]);
        __syncthreads();
        if (t < 64) {
            float a = p1b2[t], b = p2b2[t];
#pragma unroll 8
            for (int k = 0; k < 128; k++) { a += hcat[k]*p1w2[k*64+t]; b += hid[k]*p2w2[k*64+t]; }
            g_c1[t] = a; g_c2[t] = b;
        }
        return;
    }
    int r = edges[e], c = edges[EE + e];
    if (t < 64) hcat[t] = h[r*64 + t];
    else        hcat[t] = h[c*64 + (t - 64)];
    if (t < 3)  g_cdiff[e*3 + t] = x[r*3 + t] - x[c*3 + t];
    __syncthreads();
    float acc = eb1[t];
#pragma unroll 8
    for (int k = 0; k < 128; k++) acc += hcat[k] * ew1[k*128 + t];
    hid[t] = siluf(acc);
    __syncthreads();
    if (t < 64) {
        float o = eb2[t];
#pragma unroll 8
        for (int k = 0; k < 128; k++) o += hid[k] * ew2[k*64 + t];
        g_efn[e*64 + t] = o;
    }
}

// ---------------- 2. occupancy flag + compaction ----------------
__global__ void k_flag(const int* __restrict__ nbe)
{
    int m = blockIdx.x * blockDim.x + threadIdx.x;
    if (m < MM) g_map[nbe[m]*EE + nbe[MM + m]] = 1;
}

__global__ void k_compact()
{
    int cell = blockIdx.x * blockDim.x + threadIdx.x;
    if (cell < RTOT && g_map[cell] != 0) {
        int slot = atomicAdd(&g_nnz, 1);
        g_map[cell] = slot + 1;
        g_cells[slot] = cell;
    }
}

// ---------------- 3. VTV + PE + scatter, warp-per-m, v4 REDs ----------------
__global__ void k_scat(const int* __restrict__ nbe)
{
    int warp = threadIdx.x >> 5, lane = threadIdx.x & 31;
    int m = blockIdx.x*4 + warp;
    if (lane >= 24) return;           // 24 lanes x 4 f = 96 features
    int a = nbe[m], b = nbe[MM + m];
    int slot = g_map[a*EE + b] - 1;
    float v0, v1, v2, v3;
    if (lane < 8) {                   // f = lane*4 .. lane*4+3 (PE part, f<32)
        float vtv = 0.f;
#pragma unroll
        for (int d = 0; d < 3; d++) vtv += g_cdiff[a*3 + d] * g_cdiff[b*3 + d];
        int i0 = lane*2;
        float ang0 = vtv * 16.f * expf(-0.5756462732485115f * (float)i0);
        float ang1 = vtv * 16.f * expf(-0.5756462732485115f * (float)(i0 + 1));
        v0 = sinf(ang0); v1 = cosf(ang0);
        v2 = sinf(ang1); v3 = cosf(ang1);
    } else {                          // f = lane*4 .. +3 in [32,96) -> efn[f-32]
        int f0 = lane*4 - 32;
        v0 = g_efn[a*64 + f0]     * g_efn[b*64 + f0];
        v1 = g_efn[a*64 + f0 + 1] * g_efn[b*64 + f0 + 1];
        v2 = g_efn[a*64 + f0 + 2] * g_efn[b*64 + f0 + 2];
        v3 = g_efn[a*64 + f0 + 3] * g_efn[b*64 + f0 + 3];
    }
    red4(&g_Tval[(size_t)slot*96 + lane*4], v0, v1, v2, v3);
}

// ---------------- fused 2-layer MLP, W2 overlaid, float4 A-operand loads ----------------
template<int K1>
__device__ __forceinline__ void mlp_tile(float* region, float* sHid,
    const float* __restrict__ W1, const float* __restrict__ b1,
    const float* __restrict__ W2, const float* __restrict__ b2,
    float acc2[4][4])
{
    float* sA  = region;
    float* sW1 = region + 64*K1;
    int tid = threadIdx.x, ty = tid >> 4, tx = tid & 15;
    ull accp[4][4];
#pragma unroll
    for (int i = 0; i < 4; i++)
#pragma unroll
        for (int u = 0; u < 4; u++) accp[i][u] = 0ull;

    for (int kc = 0; kc < K1; kc += 32) {
        for (int i = tid*4; i < 32*128; i += 1024)
            *(float4*)&sW1[i] = *(const float4*)&W1[kc*128 + i];
        __syncthreads();
#pragma unroll
        for (int k4 = 0; k4 < 32; k4 += 4) {
            float4 a4[4];
#pragma unroll
            for (int i = 0; i < 4; i++)
                a4[i] = *(const float4*)&sA[(ty*4 + i)*K1 + kc + k4];
#pragma unroll
            for (int kk = 0; kk < 4; kk++) {
                ulonglong2 b0 = *(const ulonglong2*)&sW1[(k4+kk)*128 + tx*8];
                ulonglong2 b1v = *(const ulonglong2*)&sW1[(k4+kk)*128 + tx*8 + 4];
#pragma unroll
                for (int i = 0; i < 4; i++) {
                    float av = ((const float*)&a4[i])[kk];
                    ull ap; PACK2(ap, av, av);
                    FMA2(accp[i][0], ap, b0.x, accp[i][0]);
                    FMA2(accp[i][1], ap, b0.y, accp[i][1]);
                    FMA2(accp[i][2], ap, b1v.x, accp[i][2]);
                    FMA2(accp[i][3], ap, b1v.y, accp[i][3]);
                }
            }
        }
        __syncthreads();
    }
#pragma unroll
    for (int i = 0; i < 4; i++)
#pragma unroll
        for (int u = 0; u < 4; u++) {
            float lo, hi; UNPACK2(lo, hi, accp[i][u]);
            int j = tx*8 + u*2;
            sHid[(ty*4 + i)*128 + j]     = siluf(lo + b1[j]);
            sHid[(ty*4 + i)*128 + j + 1] = siluf(hi + b1[j + 1]);
        }
    __syncthreads();
    for (int i = tid*4; i < 128*64; i += 1024)
        *(float4*)&region[i] = *(const float4*)&W2[i];
    __syncthreads();

    ull acc2p[4][2];
#pragma unroll
    for (int i = 0; i < 4; i++) { acc2p[i][0] = 0ull; acc2p[i][1] = 0ull; }
#pragma unroll
    for (int k4 = 0; k4 < 128; k4 += 4) {
        float4 a4[4];
#pragma unroll
        for (int i = 0; i < 4; i++)
            a4[i] = *(const float4*)&sHid[(ty*4 + i)*128 + k4];
#pragma unroll
        for (int kk = 0; kk < 4; kk++) {
            ulonglong2 b = *(const ulonglong2*)&region[(k4+kk)*64 + tx*4];
#pragma unroll
            for (int i = 0; i < 4; i++) {
                float av = ((const float*)&a4[i])[kk];
                ull ap; PACK2(ap, av, av);
                FMA2(acc2p[i][0], ap, b.x, acc2p[i][0]);
                FMA2(acc2p[i][1], ap, b.y, acc2p[i][1]);
            }
        }
    }
#pragma unroll
    for (int i = 0; i < 4; i++) {
        float lo, hi;
        UNPACK2(lo, hi, acc2p[i][0]);
        acc2[i][0] = lo + b2[tx*4];     acc2[i][1] = hi + b2[tx*4 + 1];
        UNPACK2(lo, hi, acc2p[i][1]);
        acc2[i][2] = lo + b2[tx*4 + 2]; acc2[i][3] = hi + b2[tx*4 + 3];
    }
    __syncthreads();
}

// ---------------- 5. sparse MLPs: S1,S2 + row/col sums (v4 REDs) ----------------
__global__ void __launch_bounds__(256) k_smlp(
    const float* __restrict__ p1w1, const float* __restrict__ p1b1,
    const float* __restrict__ p1w2, const float* __restrict__ p1b2,
    const float* __restrict__ p2w1, const float* __restrict__ p2b1,
    const float* __restrict__ p2w2, const float* __restrict__ p2b2)
{
    extern __shared__ float smem[];
    float* sHid   = smem;            // 8192
    float* region = smem + 8192;     // 64*96 + 32*128 = 10240
    int base = blockIdx.x * 64;
    int tid = threadIdx.x, ty = tid >> 4, tx = tid & 15;
    int nnz = g_nnz;

    const float* Tp = &g_Tval[(size_t)base * 96];
    for (int i = tid*4; i < 64*96; i += 1024)
        *(float4*)&region[i] = *(const float4*)&Tp[i];
    __syncthreads();

    float4 c1v = *(const float4*)&g_c1[tx*4];
    float4 c2v = *(const float4*)&g_c2[tx*4];

    float acc2[4][4];
    mlp_tile<96>(region, sHid, p1w1, p1b1, p1w2, p1b2, acc2);
#pragma unroll
    for (int i = 0; i < 4; i++) {
        int slot = base + ty*4 + i;
        if (slot < nnz) {
            int cell = g_cells[slot];
            float v0 = acc2[i][0] - c1v.x, v1 = acc2[i][1] - c1v.y;
            float v2 = acc2[i][2] - c1v.z, v3 = acc2[i][3] - c1v.w;
            *(float4*)&g_S1[(size_t)slot*64 + tx*4] = make_float4(v0, v1, v2, v3);
            red4(&g_sb.rowS1[(cell >> 9)*64 + tx*4], v0, v1, v2, v3);
        }
    }
    __syncthreads();
    for (int i = tid*4; i < 64*96; i += 1024)
        *(float4*)&region[i] = *(const float4*)&Tp[i];
    __syncthreads();

    mlp_tile<96>(region, sHid, p2w1, p2b1, p2w2, p2b2, acc2);
#pragma unroll
    for (int i = 0; i < 4; i++) {
        int slot = base + ty*4 + i;
        if (slot < nnz) {
            int cell = g_cells[slot];
            float v0 = acc2[i][0] - c2v.x, v1 = acc2[i][1] - c2v.y;
            float v2 = acc2[i][2] - c2v.z, v3 = acc2[i][3] - c2v.w;
            *(float4*)&g_S2[(size_t)slot*64 + tx*4] = make_float4(v0, v1, v2, v3);
            red4(&g_sb.colS2[(cell & 511)*64 + tx*4], v0, v1, v2, v3);
        }
    }
}

// ---------------- 6. a_i / b_j tables (+ u0 in last block) ----------------
__global__ void k_ab(const float* __restrict__ p3w1, const float* __restrict__ p3b1)
{
    __shared__ float r[64];
    int b = blockIdx.x, t = threadIdx.x;  // 128
    if (b < 512) {
        int i = b;
        if (t < 64) r[t] = g_sb.rowS1[i*64 + t] * g_c2[t];
        __syncthreads();
        float a = 0.f;
#pragma unroll 8
        for (int f = 0; f < 64; f++) a += r[f] * p3w1[(96+f)*128 + t];
        g_atab[i*128 + t] = a;
    } else if (b < 1024) {
        int j = b - 512;
        if (t < 64) r[t] = g_sb.colS2[j*64 + t] * g_c1[t];
        __syncthreads();
        float a = 0.f;
#pragma unroll 8
        for (int f = 0; f < 64; f++) a += r[f] * p3w1[(96+f)*128 + t];
        g_btab[j*128 + t] = a;
    } else {
        if (t < 64) r[t] = 512.f * g_c1[t] * g_c2[t];
        __syncthreads();
        float u = p3b1[t];
#pragma unroll 8
        for (int f = 0; f < 64; f++) u += r[f] * p3w1[(96+f)*128 + t];
        g_u0[t] = u;
    }
}

// ---------------- 7. group slots by middle index ----------------
__global__ void k_cnt()
{
    int s = blockIdx.x * blockDim.x + threadIdx.x;
    if (s < g_nnz) {
        int cell = g_cells[s];
        atomicAdd(&g_sb.cntA[cell & 511], 1);
        atomicAdd(&g_sb.cntB[cell >> 9], 1);
    }
}

__global__ void k_scan()
{
    __shared__ int s[512];
    int t = threadIdx.x;  // 512
    s[t] = g_sb.cntA[t]; __syncthreads();
    for (int d = 1; d < 512; d <<= 1) {
        int v = (t >= d) ? s[t - d] : 0;
        __syncthreads();
        s[t] += v;
        __syncthreads();
    }
    int exc = s[t] - g_sb.cntA[t];
    g_offA[t] = exc; g_curA[t] = exc;
    __syncthreads();
    s[t] = g_sb.cntB[t]; __syncthreads();
    for (int d = 1; d < 512; d <<= 1) {
        int v = (t >= d) ? s[t - d] : 0;
        __syncthreads();
        s[t] += v;
        __syncthreads();
    }
    exc = s[t] - g_sb.cntB[t];
    g_offB[t] = exc; g_curB[t] = exc;
}

__global__ void k_fill()
{
    int s = blockIdx.x * blockDim.x + threadIdx.x;
    if (s < g_nnz) {
        int cell = g_cells[s];
        int pa = atomicAdd(&g_curA[cell & 511], 1);
        g_listA[pa] = s;
        int pb = atomicAdd(&g_curB[cell >> 9], 1);
        g_listB[pb] = s;
    }
}

// ---------------- 8. sparse-sparse product, f-split (grid 512 x 2) ----------------
__global__ void __launch_bounds__(256) k_ss()
{
    __shared__ float sA[64*32];
    __shared__ float sB[64*32];
    __shared__ int ri[64], cj[64];
    int k = blockIdx.x, tid = threadIdx.x;
    int f0 = blockIdx.y * 32;
    int cA = g_sb.cntA[k], cB = g_sb.cntB[k];
    if (cA == 0 || cB == 0) return;
    int oA = g_offA[k], oB = g_offB[k];

    for (int a0 = 0; a0 < cA; a0 += 64) {
        int nA = min(64, cA - a0);
        __syncthreads();
        for (int x = tid; x < nA*32; x += 256) {
            int r = x >> 5;
            int slot = g_listA[oA + a0 + r];
            sA[x] = g_S1[(size_t)slot*64 + f0 + (x & 31)];
        }
        for (int r = tid; r < nA; r += 256) ri[r] = g_cells[g_listA[oA + a0 + r]] >> 9;
        for (int b0 = 0; b0 < cB; b0 += 64) {
            int nB = min(64, cB - b0);
            __syncthreads();
            for (int x = tid; x < nB*32; x += 256) {
                int c = x >> 5;
                int slot = g_listB[oB + b0 + c];
                sB[x] = g_S2[(size_t)slot*64 + f0 + (x & 31)];
            }
            for (int c = tid; c < nB; c += 256) cj[c] = g_cells[g_listB[oB + b0 + c]] & 511;
            __syncthreads();
            int fg = tid & 7, pc = tid >> 3;
            for (int r = 0; r < nA; r++) {
                float4 av = *(const float4*)&sA[r*32 + fg*4];
                int ibase = ri[r];
                for (int c = pc; c < nB; c += 32) {
                    float4 bv = *(const float4*)&sB[c*32 + fg*4];
                    red4(&g_SS[((size_t)ibase*512 + cj[c])*64 + f0 + fg*4],
                         av.x*bv.x, av.y*bv.y, av.z*bv.z, av.w*bv.w);
                }
            }
        }
    }
}

// ---------------- 9. Ztc[slot] = W1t^T Tval[slot] ----------------
__global__ void k_tc(const float* __restrict__ p3w1)
{
    __shared__ float tv[96];
    int slot = blockIdx.x, t = threadIdx.x;  // 128
    if (slot >= g_nnz) return;
    if (t < 96) tv[t] = g_Tval[(size_t)slot*96 + t];
    __syncthreads();
    float acc = 0.f;
#pragma unroll 8
    for (int k = 0; k < 96; k++) acc += tv[k] * p3w1[k*128 + t];
    g_Ztc[(size_t)slot*128 + t] = acc;
}

// ---------------- 10. FUSED: Z-GEMM (f32x2) + additive terms + SiLU + reductions ----------------
__global__ void __launch_bounds__(256) k_fused(const float* __restrict__ p3w1)
{
    extern __shared__ float dsm[];
    float* sA   = dsm;                  // [64][68]
    float* sB   = sA + 64*68;           // [64][128]  W1m
    float* srow = sB + 8192;            // [128]
    int*  sslot = (int*)(srow + 128);   // [64]

    size_t base = (size_t)blockIdx.x * 64;
    int i_glob = (int)(base >> 9);
    int j0 = (int)(base & 511);
    int tid = threadIdx.x;

    for (int x = tid*4; x < 4096; x += 1024) {
        float4 v = *(const float4*)&g_SS[base*64 + x];
        int cell = x >> 6, k = x & 63;
        *(float4*)&sA[cell*68 + k] = v;
    }
    for (int x = tid*4; x < 8192; x += 1024)
        *(float4*)&sB[x] = *(const float4*)&p3w1[96*128 + x];
    if (tid < 128) srow[tid] = 0.f;
    if (tid < 64)  sslot[tid] = g_map[base + tid] - 1;
    __syncthreads();

    int ty = tid >> 4, tx = tid & 15;
    ull accp[4][4];
#pragma unroll
    for (int i = 0; i < 4; i++)
#pragma unroll
        for (int u = 0; u < 4; u++) accp[i][u] = 0ull;

#pragma unroll 16
    for (int k = 0; k < 64; k++) {
        ulonglong2 b0 = *(const ulonglong2*)&sB[k*128 + tx*8];
        ulonglong2 b1 = *(const ulonglong2*)&sB[k*128 + tx*8 + 4];
#pragma unroll
        for (int i = 0; i < 4; i++) {
            float av = sA[(ty*4 + i)*68 + k];
            ull ap; PACK2(ap, av, av);
            FMA2(accp[i][0], ap, b0.x, accp[i][0]);
            FMA2(accp[i][1], ap, b0.y, accp[i][1]);
            FMA2(accp[i][2], ap, b1.x, accp[i][2]);
            FMA2(accp[i][3], ap, b1.y, accp[i][3]);
        }
    }

    float add[8];
    {
        float4 u0a = *(const float4*)&g_u0[tx*8];
        float4 u0b = *(const float4*)&g_u0[tx*8 + 4];
        float4 aa  = *(const float4*)&g_atab[i_glob*128 + tx*8];
        float4 ab  = *(const float4*)&g_atab[i_glob*128 + tx*8 + 4];
        add[0]=u0a.x+aa.x; add[1]=u0a.y+aa.y; add[2]=u0a.z+aa.z; add[3]=u0a.w+aa.w;
        add[4]=u0b.x+ab.x; add[5]=u0b.y+ab.y; add[6]=u0b.z+ab.z; add[7]=u0b.w+ab.w;
    }

    float rsum[8];
#pragma unroll
    for (int u = 0; u < 8; u++) rsum[u] = 0.f;

#pragma unroll
    for (int i = 0; i < 4; i++) {
        int r = ty*4 + i;
        int j = j0 + r;
        float4 b0 = *(const float4*)&g_btab[j*128 + tx*8];
        float4 b1 = *(const float4*)&g_btab[j*128 + tx*8 + 4];
        float zb[8] = {b0.x, b0.y, b0.z, b0.w, b1.x, b1.y, b1.z, b1.w};
        int slot = sslot[r];
        if (slot >= 0) {
            float4 t0 = *(const float4*)&g_Ztc[(size_t)slot*128 + tx*8];
            float4 t1 = *(const float4*)&g_Ztc[(size_t)slot*128 + tx*8 + 4];
            zb[0]+=t0.x; zb[1]+=t0.y; zb[2]+=t0.z; zb[3]+=t0.w;
            zb[4]+=t1.x; zb[5]+=t1.y; zb[6]+=t1.z; zb[7]+=t1.w;
        }
        float acc[8];
#pragma unroll
        for (int u = 0; u < 4; u++) {
            float lo, hi; UNPACK2(lo, hi, accp[i][u]);
            acc[u*2] = lo; acc[u*2+1] = hi;
        }
        float hv[8];
#pragma unroll
        for (int u = 0; u < 8; u++) {
            hv[u] = siluf(acc[u] + add[u] + zb[u]);
            rsum[u] += hv[u];
        }
        if (j == i_glob) {
            *(float4*)&g_Hdiag[i_glob*128 + tx*8]     = make_float4(hv[0], hv[1], hv[2], hv[3]);
            *(float4*)&g_Hdiag[i_glob*128 + tx*8 + 4] = make_float4(hv[4], hv[5], hv[6], hv[7]);
        }
        red4(&g_sb.Hcol[j*128 + tx*8],     hv[0], hv[1], hv[2], hv[3]);
        red4(&g_sb.Hcol[j*128 + tx*8 + 4], hv[4], hv[5], hv[6], hv[7]);
    }
#pragma unroll
    for (int u = 0; u < 8; u++) atomicAdd(&srow[tx*8 + u], rsum[u]);
    __syncthreads();
    if (tid < 32)
        red4(&g_sb.Hrow[i_glob*128 + tid*4],
             srow[tid*4], srow[tid*4+1], srow[tid*4+2], srow[tid*4+3]);
}

// ---------------- 11. apply W2 to aggregates ----------------
__global__ void k_ign(const float* __restrict__ w2, const float* __restrict__ b2)
{
    __shared__ float hd[128], hr[128], hc[128];
    int e = blockIdx.x, t = threadIdx.x;  // 128 threads, 513 blocks
    if (e < 512) {
        hd[t] = g_Hdiag[e*128 + t];
        hr[t] = g_sb.Hrow[e*128 + t];
        hc[t] = g_sb.Hcol[e*128 + t];
        __syncthreads();
        if (t < 64) {
            float d = 0.f, r = 0.f, c = 0.f;
#pragma unroll 8
            for (int k = 0; k < 128; k++) {
                float w = w2[k*64 + t];
                d += hd[k]*w; r += hr[k]*w; c += hc[k]*w;
            }
            float bb = b2[t];
            g_diag[e*64 + t] = d + bb;
            g_row[e*64 + t]  = r + 512.f*bb;
            g_col[e*64 + t]  = c + 512.f*bb;
        }
    } else {
        float st = 0.f, sr = 0.f;
        for (int i = 0; i < 512; i++) { st += g_sb.Hrow[i*128 + t]; sr += g_Hdiag[i*128 + t]; }
        hd[t] = st; hr[t] = sr;
        __syncthreads();
        if (t < 64) {
            float a = 0.f, b = 0.f;
#pragma unroll 8
            for (int k = 0; k < 128; k++) { float w = w2[k*64 + t]; a += hd[k]*w; b += hr[k]*w; }
            g_tot[t] = a + 262144.f*b2[t];
            g_tr[t]  = b + 512.f*b2[t];
        }
    }
}

// ---------------- 12. IGN linear + coord weights + segment scatter (fused) ----------------
__global__ void k_coord(const int* __restrict__ edges,
                        const float* __restrict__ ign_w, const float* __restrict__ ign_b,
                        const float* __restrict__ cw1, const float* __restrict__ cb1,
                        const float* __restrict__ cw2)
{
    __shared__ float feat[320];
    __shared__ float nb[64];
    __shared__ float red[128];
    int e = blockIdx.x, t = threadIdx.x;   // 128
    if (t < 64) {
        feat[t]       = g_diag[e*64 + t];
        feat[64 + t]  = g_row[e*64 + t];
        feat[128 + t] = g_col[e*64 + t];
        feat[192 + t] = g_tot[t];
        feat[256 + t] = g_tr[t];
    }
    __syncthreads();
    if (t < 64) {
        float o = ign_b[t];
#pragma unroll 8
        for (int k = 0; k < 320; k++) o += feat[k] * ign_w[k*64 + t];
        nb[t] = o;
    }
    __syncthreads();
    float acc = cb1[t];
#pragma unroll 8
    for (int k = 0; k < 64; k++) acc += nb[k] * cw1[k*128 + t];
    red[t] = siluf(acc) * cw2[t];
    __syncthreads();
    for (int st = 64; st > 0; st >>= 1) {
        if (t < st) red[t] += red[t + st];
        __syncthreads();
    }
    float w = red[0];
    int r = edges[e];
    if (t < 3)  atomicAdd(&g_sb.segx[r*3 + t], g_cdiff[e*3 + t] * w);
    if (t == 3) atomicAdd(&g_sb.cnt[r], 1.f);
    if (t >= 64) atomicAdd(&g_sb.nbt0[r*64 + (t - 64)], nb[t - 64]);
}

// ---------------- 13. node update + coord finalize + edge_attr copy (fused) ----------------
__global__ void k_node(const float* __restrict__ h, const float* __restrict__ x,
                       const float* __restrict__ nw1, const float* __restrict__ nb1,
                       const float* __restrict__ nw2, const float* __restrict__ nb2,
                       const float* __restrict__ ea, float* __restrict__ out)
{
    __shared__ float a[64];
    __shared__ float hid[128];
    int n = blockIdx.x, t = threadIdx.x;   // 128
    if (n >= NN) {   // edge_attr copy: blocks NN..NN+15 cover 2048 floats
        int i = (n - NN)*128 + t;
        out[NN*64 + NN*3 + i] = ea[i];
        return;
    }
    if (t < 64) a[t] = g_sb.nbt0[n*64 + t];
    __syncthreads();
    float acc = nb1[t];
#pragma unroll 8
    for (int k = 0; k < 64; k++) acc += a[k] * nw1[k*128 + t];
    hid[t] = siluf(acc);
    __syncthreads();
    if (t < 64) {
        float o = nb2[t];
#pragma unroll 8
        for (int k = 0; k < 128; k++) o += hid[k] * nw2[k*64 + t];
        out[n*64 + t] = h[n*64 + t] + o;
    } else if (t < 67) {
        int d = t - 64;
        float c = g_sb.cnt[n];
        if (c < 1.f) c = 1.f;
        out[NN*64 + n*3 + d] = x[n*3 + d] + g_sb.segx[n*3 + d] / c;
    }
}

// ---------------- host ----------------
extern "C" void kernel_launch(void* const* d_in, const int* in_sizes, int n_in,
                              void* d_out, int out_size)
{
    const float* h     = (const float*)d_in[0];
    const float* x     = (const float*)d_in[1];
    const int*   edges = (const int*)d_in[2];
    const int*   nbe   = (const int*)d_in[3];
    const float* ea    = (const float*)d_in[4];
    int wb = n_in - 25;
    const float* ew1  = (const float*)d_in[wb + 0];
    const float* eb1  = (const float*)d_in[wb + 1];
    const float* ew2  = (const float*)d_in[wb + 2];
    const float* eb2  = (const float*)d_in[wb + 3];
    const float* p1w1 = (const float*)d_in[wb + 4];
    const float* p1b1 = (const float*)d_in[wb + 5];
    const float* p1w2 = (const float*)d_in[wb + 6];
    const float* p1b2 = (const float*)d_in[wb + 7];
    const float* p2w1 = (const float*)d_in[wb + 8];
    const float* p2b1 = (const float*)d_in[wb + 9];
    const float* p2w2 = (const float*)d_in[wb + 10];
    const float* p2b2 = (const float*)d_in[wb + 11];
    const float* p3w1 = (const float*)d_in[wb + 12];
    const float* p3b1 = (const float*)d_in[wb + 13];
    const float* p3w2 = (const float*)d_in[wb + 14];
    const float* p3b2 = (const float*)d_in[wb + 15];
    const float* ignw = (const float*)d_in[wb + 16];
    const float* ignb = (const float*)d_in[wb + 17];
    const float* cw1  = (const float*)d_in[wb + 18];
    const float* cb1  = (const float*)d_in[wb + 19];
    const float* cw2  = (const float*)d_in[wb + 20];
    const float* ndw1 = (const float*)d_in[wb + 21];
    const float* ndb1 = (const float*)d_in[wb + 22];
    const float* ndw2 = (const float*)d_in[wb + 23];
    const float* ndb2 = (const float*)d_in[wb + 24];
    float* out = (float*)d_out;

    int smlp_smem  = (8192 + 64*96 + 32*128) * 4;        // 72 KB
    int fused_smem = (64*68 + 8192 + 128 + 64) * 4;
    cudaFuncSetAttribute(k_smlp,  cudaFuncAttributeMaxDynamicSharedMemorySize, smlp_smem);
    cudaFuncSetAttribute(k_fused, cudaFuncAttributeMaxDynamicSharedMemorySize, fused_smem);

    void* p;
    cudaGetSymbolAddress(&p, g_map);  cudaMemsetAsync(p, 0, sizeof(int)*RTOT, 0);
    cudaGetSymbolAddress(&p, g_nnz);  cudaMemsetAsync(p, 0, sizeof(int), 0);
    cudaGetSymbolAddress(&p, g_Tval); cudaMemsetAsync(p, 0, sizeof(float)*(size_t)SMAX*96, 0);
    cudaGetSymbolAddress(&p, g_SS);   cudaMemsetAsync(p, 0, sizeof(float)*(size_t)RTOT*64, 0);
    cudaGetSymbolAddress(&p, g_sb);   cudaMemsetAsync(p, 0, sizeof(SmallBufs), 0);

    k_edge<<<EE + 1, 128>>>(h, x, edges, ew1, eb1, ew2, eb2,
                            p1b1, p1w2, p1b2, p2b1, p2w2, p2b2);
    k_flag<<<MM/256, 256>>>(nbe);
    k_compact<<<RTOT/256, 256>>>();
    k_scat<<<MM/4, 128>>>(nbe);
    k_smlp<<<SMAX/64, 256, smlp_smem>>>(p1w1, p1b1, p1w2, p1b2,
                                        p2w1, p2b1, p2w2, p2b2);
    k_ab<<<1025, 128>>>(p3w1, p3b1);
    k_tc<<<SMAX, 128>>>(p3w1);
    k_cnt<<<SMAX/256, 256>>>();
    k_scan<<<1, 512>>>();
    k_fill<<<SMAX/256, 256>>>();
    k_ss<<<dim3(EE, 2), 256>>>();
    k_fused<<<RTOT/64, 256, fused_smem>>>(p3w1);
    k_ign<<<513, 128>>>(p3w2, p3b2);
    k_coord<<<EE, 128>>>(edges, ignw, ignb, cw1, cb1, cw2);
    k_node<<<NN + 16, 128>>>(h, x, ndw1, ndb1, ndw2, ndb2, ea, out);
}